// round 6
// baseline (speedup 1.0000x reference)
#include <cuda_runtime.h>

// Problem constants (fixed by the reference build)
#define Bn 4
#define Cn 32
#define Ln 256
#define Mn 256
#define Fn 8
#define Nw 64
#define FP (Fn/2)     // f-pairs for f32x2 packing

typedef unsigned long long u64;

__device__ __forceinline__ u64 pack2(float lo, float hi) {
    u64 r;
    asm("mov.b64 %0, {%1, %2};" : "=l"(r) : "f"(lo), "f"(hi));
    return r;
}
__device__ __forceinline__ void ffma2(u64& d, u64 a, u64 b) {
    asm("fma.rn.f32x2 %0, %1, %2, %0;" : "+l"(d) : "l"(a), "l"(b));
}
__device__ __forceinline__ float2 unpack2(u64 v) {
    float2 r;
    asm("mov.b64 {%0, %1}, %2;" : "=f"(r.x), "=f"(r.y) : "l"(v));
    return r;
}

// CTA: 64 threads, one (l, b). Thread t owns m = 4t..4t+3 (float4 x loads),
// all 8 f (4 f32x2 pairs), reduced over c = 0..31.
__global__ __launch_bounds__(64, 8)
void sphereconv_kernel(const float* __restrict__ xr,
                       const float* __restrict__ xi,
                       const float* __restrict__ wr,
                       const float* __restrict__ wi,
                       float* __restrict__ out)
{
    // Per (f-pair p, c): float4 {wr_{2p}, wr_{2p+1}, wi_{2p}, wi_{2p+1}}  (2 KB)
    __shared__ __align__(16) float s_w[FP * Cn * 4];

    const int l = blockIdx.x;           // 0..255
    const int b = blockIdx.y;           // 0..3
    const int t = threadIdx.x;          // 0..63

    // ---- Phase 1: interpolate weights for this l (F*C = 256, 4 per thread) ----
    {
        float tt = ((float)l / (float)(Ln - 1)) * (float)(Nw - 1);
        int lo = (int)tt;                       // tt >= 0 -> trunc == floor
        lo = lo > Nw - 2 ? Nw - 2 : lo;
        float frac = tt - (float)lo;
        #pragma unroll
        for (int e = t; e < Fn * Cn; e += 64) {
            int f = e >> 5, c = e & 31;
            int base = (f * Cn + c) * Nw;       // w shape (F, C, N, 1)
            float wre = wr[base + lo] * (1.0f - frac) + wr[base + lo + 1] * frac;
            float wim = wi[base + lo] * (1.0f - frac) + wi[base + lo + 1] * frac;
            int p = f >> 1, lane = f & 1;
            s_w[((p * Cn + c) << 2) + lane]     = wre;
            s_w[((p * Cn + c) << 2) + 2 + lane] = wim;
        }
    }
    __syncthreads();

    const ulonglong2* __restrict__ pw = (const ulonglong2*)s_w;

    const size_t strideC  = (size_t)Ln * Mn;            // 65536 floats
    const size_t strideC4 = strideC / 4;                // in float4 units
    const float4* __restrict__ xr4 =
        (const float4*)(xr + (size_t)b * Cn * strideC + (size_t)l * Mn) + t;
    const float4* __restrict__ xi4 =
        (const float4*)(xi + (size_t)b * Cn * strideC + (size_t)l * Mn) + t;

    u64 ar[4][FP], ai[4][FP];
    #pragma unroll
    for (int mm = 0; mm < 4; mm++)
        #pragma unroll
        for (int p = 0; p < FP; p++) { ar[mm][p] = 0ULL; ai[mm][p] = 0ULL; }

    // Double-buffered chunks of 2 c's: [buf][c-in-chunk]
    float4 bR[2][2], bI[2][2];

    auto loadchunk = [&](int buf, int k) {
        const size_t c0 = (size_t)(k * 2);
        bR[buf][0] = __ldg(xr4 + c0 * strideC4);
        bR[buf][1] = __ldg(xr4 + (c0 + 1) * strideC4);
        bI[buf][0] = __ldg(xi4 + c0 * strideC4);
        bI[buf][1] = __ldg(xi4 + (c0 + 1) * strideC4);
    };

    auto compute = [&](int buf, int k) {
        #pragma unroll
        for (int cl = 0; cl < 2; cl++) {
            const int c = k * 2 + cl;
            const float4 xrv = bR[buf][cl];
            const float4 xiv = bI[buf][cl];
            ulonglong2 ww[FP];
            #pragma unroll
            for (int p = 0; p < FP; p++) ww[p] = pw[p * Cn + c];  // LDS.128 broadcast

            #pragma unroll
            for (int mm = 0; mm < 4; mm++) {
                const float xrs = (&xrv.x)[mm];
                const float xis = (&xiv.x)[mm];
                const u64 xr2  = pack2(xrs, xrs);
                const u64 xi2  = pack2(xis, xis);
                const float nx = -xis;
                const u64 nxi2 = pack2(nx, nx);
                #pragma unroll
                for (int p = 0; p < FP; p++) {
                    ffma2(ar[mm][p], ww[p].x, xr2);    // +wr*xr
                    ffma2(ar[mm][p], ww[p].y, nxi2);   // -wi*xi
                    ffma2(ai[mm][p], ww[p].x, xi2);    // +wr*xi
                    ffma2(ai[mm][p], ww[p].y, xr2);    // +wi*xr
                }
            }
        }
    };

    loadchunk(0, 0);
    #pragma unroll 1
    for (int k = 0; k < 16; k += 2) {
        if (k + 1 < 16) loadchunk(1, k + 1);
        compute(0, k);
        if (k + 2 < 16) loadchunk(0, k + 2);
        compute(1, k + 1);
    }

    // ---- Epilogue: mean over C, scale sqrt(1+l), relu real part, store ----
    const float sc = sqrtf(1.0f + (float)l) * (1.0f / (float)Cn);
    const size_t lm      = (size_t)Ln * Mn;
    const size_t partOff = (size_t)Bn * Fn * lm;
    const int m0 = t << 2;
    const size_t obase = (((size_t)b * Fn * Ln) + l) * Mn + m0;   // f=0, real

    #pragma unroll
    for (int p = 0; p < FP; p++) {
        float4 vre, vro, vie, vio;   // even-f / odd-f, real / imag, 4 m's
        #pragma unroll
        for (int mm = 0; mm < 4; mm++) {
            const float2 r2 = unpack2(ar[mm][p]);
            const float2 i2 = unpack2(ai[mm][p]);
            (&vre.x)[mm] = fmaxf(r2.x * sc, 0.0f);
            (&vro.x)[mm] = fmaxf(r2.y * sc, 0.0f);
            (&vie.x)[mm] = i2.x * sc;
            (&vio.x)[mm] = i2.y * sc;
        }
        *(float4*)(out + obase + (size_t)(2 * p)     * lm)           = vre;
        *(float4*)(out + obase + (size_t)(2 * p + 1) * lm)           = vro;
        *(float4*)(out + obase + (size_t)(2 * p)     * lm + partOff) = vie;
        *(float4*)(out + obase + (size_t)(2 * p + 1) * lm + partOff) = vio;
    }
}

extern "C" void kernel_launch(void* const* d_in, const int* in_sizes, int n_in,
                              void* d_out, int out_size) {
    const float* xr = (const float*)d_in[0];
    const float* xi = (const float*)d_in[1];
    const float* wr = (const float*)d_in[2];
    const float* wi = (const float*)d_in[3];
    float* out = (float*)d_out;

    dim3 grid(Ln, Bn);   // (l, b) = 1024 CTAs of 64 threads
    sphereconv_kernel<<<grid, 64>>>(xr, xi, wr, wi, out);
}